// round 13
// baseline (speedup 1.0000x reference)
#include <cuda_runtime.h>
#include <cuda_fp16.h>
#include <cstdint>

// ================= problem constants =================
#define NB_ROWS  16384
#define N_IN     256
#define N_OUT    256
#define N_BASES  31
#define MTILE    112                 // rows per CTA
#define RPW      7                   // rows per warp (16 warps)
#define NCTA     147                 // ceil(16384/112)
#define BROWS    (NCTA * MTILE)      // 16464 padded rows
#define THREADS  512

// W2 slice: 33 j-rows (32 real + zero row for j=32) x 256 fp16 = 16896 B
#define SLICE    16896
#define STAGE    (4 * SLICE)         // 67584 B: 4 i per stage
#define SM_MBAR  (2 * STAGE)
#define SMEM_TOTAL (2 * STAGE + 64)

// ================= device scratch =================
__device__ __align__(16) __half   g_W2T[N_IN * 33 * N_OUT];  // [i][j<=32][o] fp16, 4.3 MB
__device__ __align__(16) __half   g_BW16[N_IN * N_OUT];      // [i][o] fp16
__device__ __align__(16) uint32_t g_RJ2[BROWS * N_IN];       // [row][i]: (j<<16)|rx_fp16
__device__ unsigned int g_minU[N_IN];
__device__ unsigned int g_maxU[N_IN];
__device__ float        g_minv[N_IN];
__device__ float        g_rcp[N_IN];

// ================= helpers =================
__device__ __forceinline__ unsigned int enc_f(float f) {
    unsigned int u = __float_as_uint(f);
    return (u & 0x80000000u) ? ~u : (u | 0x80000000u);
}
__device__ __forceinline__ float dec_f(unsigned int e) {
    unsigned int u = (e & 0x80000000u) ? (e ^ 0x80000000u) : ~e;
    return __uint_as_float(u);
}
__device__ __forceinline__ uint32_t smem_u32(const void* p) {
    uint32_t a;
    asm("{ .reg .u64 t; cvta.to.shared.u64 t, %1; cvt.u32.u64 %0, t; }" : "=r"(a) : "l"(p));
    return a;
}
__device__ __forceinline__ unsigned long long pk2(float a, float b) {
    unsigned long long r;
    asm("mov.b64 %0, {%1, %2};" : "=l"(r) : "f"(a), "f"(b));
    return r;
}
__device__ __forceinline__ unsigned long long pku(uint32_t a, uint32_t b) {
    unsigned long long r;
    asm("mov.b64 %0, {%1, %2};" : "=l"(r) : "r"(a), "r"(b));
    return r;
}
__device__ __forceinline__ void fmaf2(unsigned long long& d, unsigned long long a, unsigned long long b) {
    asm("fma.rn.f32x2 %0, %1, %2, %0;" : "+l"(d) : "l"(a), "l"(b));
}
__device__ __forceinline__ float lo32(unsigned long long v) {
    return __uint_as_float((unsigned int)(v & 0xFFFFFFFFull));
}
__device__ __forceinline__ float hi32(unsigned long long v) {
    return __uint_as_float((unsigned int)(v >> 32));
}
__device__ __forceinline__ void hadd2a(uint32_t& acc, uint32_t v) {
    asm("add.rn.f16x2 %0, %1, %0;" : "+r"(acc) : "r"(v));
}
__device__ __forceinline__ void hfma2a(uint32_t& acc, uint32_t a, uint32_t b) {
    asm("fma.rn.f16x2 %0, %1, %2, %0;" : "+r"(acc) : "r"(a), "r"(b));
}
// packed fp16x2 -> f32x2 pair equal to (v_lo, v_hi) * 2^-112, EXACT (ALU only).
// f32bits = sign | ((fp16 exp+mant) >> 3 masked into the f32 exp/mant fields).
// Mask AFTER the shift so the sign bit cannot leak into the exponent field.
__device__ __forceinline__ unsigned long long h2f2_pre(uint32_t h) {
    uint32_t s = h << 16;              // lo half positioned at top
    uint32_t m = h & 0xFFFF0000u;      // hi half isolated
    uint32_t lo = ((s >> 3) & 0x0FFFE000u) | (s & 0x80000000u);
    uint32_t hi = ((m >> 3) & 0x0FFFE000u) | (m & 0x80000000u);
    return pku(lo, hi);
}

#define MBAR_INIT(a, c)  asm volatile("mbarrier.init.shared.b64 [%0], %1;" :: "r"(a), "r"(c) : "memory")
#define MBAR_EXPECT(a, b) asm volatile("mbarrier.arrive.expect_tx.shared.b64 _, [%0], %1;" :: "r"(a), "r"(b) : "memory")
#define MBAR_WAIT(a, ph) do {                                                        \
    uint32_t _m = (a), _p = (ph), _d;                                                \
    asm volatile("{\n\t.reg .pred p;\n\t"                                            \
        "mbarrier.try_wait.parity.acquire.cta.shared::cta.b64 p, [%1], %2;\n\t"      \
        "selp.b32 %0,1,0,p;\n\t}" : "=r"(_d) : "r"(_m), "r"(_p) : "memory");         \
    if (!_d) {                                                                       \
        asm volatile("{\n\t.reg .pred P1;\n\tWL_%=:\n\t"                             \
            "mbarrier.try_wait.parity.acquire.cta.shared::cta.b64 P1, [%0], %1, 0x989680;\n\t" \
            "@P1 bra.uni WD_%=;\n\tbra.uni WL_%=;\n\tWD_%=:\n\t}"                    \
            :: "r"(_m), "r"(_p) : "memory");                                         \
    }                                                                                \
} while (0)
#define BULK_CP(dst, src, bytes, mbar) \
    asm volatile("cp.async.bulk.shared::cluster.global.mbarrier::complete_tx::bytes [%0], [%1], %2, [%3];" \
        :: "r"(dst), "l"(src), "r"(bytes), "r"(mbar) : "memory")

// ================= prep kernels =================
__global__ void k_init() {
    int t = threadIdx.x;
    g_minU[t] = 0xFFFFFFFFu;
    g_maxU[t] = 0x00000000u;
}

__global__ void k_minmax(const float* __restrict__ x) {
    int c  = threadIdx.x;
    int r0 = blockIdx.x * 128;
    float mn = __int_as_float(0x7f800000);
    float mx = __int_as_float(0xff800000);
    for (int r = r0; r < r0 + 128; r++) {
        float v = x[r * N_IN + c];
        mn = fminf(mn, v);
        mx = fmaxf(mx, v);
    }
    atomicMin(&g_minU[c], enc_f(mn));
    atomicMax(&g_maxU[c], enc_f(mx));
}

__global__ void k_denom() {   // XLA rewrites div(A,bcast(B)) -> mul(A,bcast(1/B))
    int i = threadIdx.x;
    float mn = dec_f(g_minU[i]);
    float mx = dec_f(g_maxU[i]);
    float d  = __fadd_rn(__fsub_rn(mx, mn), 1e-8f);
    g_minv[i] = mn;
    g_rcp[i]  = __frcp_rn(d);
}

// bucketize + relu fp16 -> g_RJ2[row][i] (coalesced both ways)
__global__ void k_rxj(const float* __restrict__ x) {
    int i  = threadIdx.x;
    int r0 = blockIdx.x * 8;
    float mn = g_minv[i];
    float rc = g_rcp[i];
#pragma unroll
    for (int k = 0; k < 8; k++) {
        int idx = (r0 + k) * N_IN + i;
        float v  = x[idx];
        float xn = __fmul_rn(__fsub_rn(v, mn), rc);   // bit-matches reference
        int j = (int)(xn * 32.0f);
        j = min(max(j, 0), 32);
        unsigned short h = __half_as_ushort(__float2half_rn(fmaxf(v, 0.0f)));
        g_RJ2[idx] = ((uint32_t)j << 16) | (uint32_t)h;
    }
}

// pad rows [16384, 16464): j=32 (zero W2 row), rx=0
__global__ void k_pad() {
    g_RJ2[(NB_ROWS + blockIdx.x) * N_IN + threadIdx.x] = (32u << 16);
}

// transpose base_weight [o][i] -> g_BW16 [i][o] fp16
__global__ void k_bw16(const float* __restrict__ bw) {
    __shared__ float s[32][33];
    int tx = threadIdx.x, ty = threadIdx.y;
    int a0 = blockIdx.y * 32;   // o
    int b0 = blockIdx.x * 32;   // i
#pragma unroll
    for (int k = 0; k < 4; k++)
        s[ty + 8 * k][tx] = bw[(a0 + ty + 8 * k) * N_IN + b0 + tx];
    __syncthreads();
#pragma unroll
    for (int k = 0; k < 4; k++)
        g_BW16[(b0 + ty + 8 * k) * N_OUT + a0 + tx] = __float2half_rn(s[tx][ty + 8 * k]);
}

// W2T[i][j<=32][o] fp16 (j=32 row is zeros)
__global__ void k_w2(const float* __restrict__ sw, const float* __restrict__ sc) {
    int i = blockIdx.x;
    int o = threadIdx.x;
    float s = sc[o * N_IN + i];
    float w[N_BASES];
#pragma unroll
    for (int k = 0; k < N_BASES; k++)
        w[k] = sw[o * (N_IN * N_BASES) + i * N_BASES + k] * s;
    __half* dst = g_W2T + (size_t)i * 33 * N_OUT + o;
#pragma unroll
    for (int j = 0; j < 32; j++) {
        float a = 0.0f;
#pragma unroll
        for (int l = 0; l < 5; l++) {
            int shift = j >> (5 - l);
            int half  = (j >> (4 - l)) & 1;
            int k     = (1 << l) - 1 + shift;
            a += half ? -w[k] : w[k];
        }
        dst[j * N_OUT] = __float2half_rn(a);
    }
    dst[32 * N_OUT] = __ushort_as_half(0);   // zero row for j == 32
}

// ================= main kernel =================
// 147 CTAs x 512 threads (16 warps). lane o8 -> 8 outputs; warp w -> 7 rows.
// Stage fill: one cp.async.bulk per 4-i stage, double-buffered w/ mbarriers.
// fp16 group accumulate (HADD2/HFMA2); every 4 i, flush to f32x2 via the exact
// ALU shift trick + fma-by-2^112 — NO conversion-pipe instructions anywhere.
__global__ __launch_bounds__(THREADS, 1) void k_main(float* __restrict__ out) {
    extern __shared__ char smem[];
    const uint32_t sb = smem_u32(smem);
    const int tid   = threadIdx.x;
    const int o8    = tid & 31;
    const int w     = tid >> 5;
    const int rbase = blockIdx.x * MTILE + w * RPW;
    const unsigned long long c112 = pk2(__uint_as_float(0x77800000u),   // 2^112
                                        __uint_as_float(0x77800000u));

    if (tid == 0) {
        MBAR_INIT(sb + SM_MBAR,     1);
        MBAR_INIT(sb + SM_MBAR + 8, 1);
    }
    __syncthreads();

    unsigned long long accf[RPW][4];
    uint32_t acch[RPW][4];
#pragma unroll
    for (int r = 0; r < RPW; r++)
#pragma unroll
        for (int k = 0; k < 4; k++) { accf[r][k] = 0ull; acch[r][k] = 0u; }

    const char* w2 = reinterpret_cast<const char*>(g_W2T);
    if (tid == 0) {
        MBAR_EXPECT(sb + SM_MBAR, STAGE);
        BULK_CP(sb, w2, STAGE, sb + SM_MBAR);
    }

    for (int ib = 0; ib < 64; ib++) {
        __syncthreads();                       // readers of the other stage done
        if (tid == 0 && ib + 1 < 64) {
            uint32_t mb = sb + SM_MBAR + 8 * ((ib + 1) & 1);
            MBAR_EXPECT(mb, STAGE);
            BULK_CP(sb + ((ib + 1) & 1) * STAGE, w2 + (size_t)(ib + 1) * STAGE, STAGE, mb);
        }
        MBAR_WAIT(sb + SM_MBAR + 8 * (ib & 1), (ib >> 1) & 1);
        const uint32_t stg = sb + (ib & 1) * STAGE;

        // base weights for the 4 i of this stage
        uint4 bwv[4];
#pragma unroll
        for (int u = 0; u < 4; u++)
            bwv[u] = *reinterpret_cast<const uint4*>(
                reinterpret_cast<const char*>(g_BW16) + (ib * 4 + u) * 512 + o8 * 16);

#pragma unroll
        for (int r = 0; r < RPW; r++) {
            // one uniform LDG.128: rj for the 4 i of this stage, row rbase+r
            uint4 q = __ldg(reinterpret_cast<const uint4*>(g_RJ2 + (size_t)(rbase + r) * N_IN) + ib);
            uint32_t qa[4] = { q.x, q.y, q.z, q.w };
#pragma unroll
            for (int u = 0; u < 4; u++) {
                uint32_t rj = qa[u];
                uint32_t a  = stg + u * SLICE + (rj >> 16) * 512 + o8 * 16;  // j==32 -> zero row
                uint4 gv;
                asm("ld.shared.v4.u32 {%0,%1,%2,%3}, [%4];"
                    : "=r"(gv.x), "=r"(gv.y), "=r"(gv.z), "=r"(gv.w) : "r"(a));
                uint32_t rxd;
                asm("prmt.b32 %0, %1, %1, 0x1010;" : "=r"(rxd) : "r"(rj));   // splat rx half
                hadd2a(acch[r][0], gv.x);  hfma2a(acch[r][0], bwv[u].x, rxd);
                hadd2a(acch[r][1], gv.y);  hfma2a(acch[r][1], bwv[u].y, rxd);
                hadd2a(acch[r][2], gv.z);  hfma2a(acch[r][2], bwv[u].z, rxd);
                hadd2a(acch[r][3], gv.w);  hfma2a(acch[r][3], bwv[u].w, rxd);
            }
        }
        // flush fp16 group (4 i) into f32 accumulators — ALU unpack + exact fma rescale
#pragma unroll
        for (int r = 0; r < RPW; r++)
#pragma unroll
            for (int k = 0; k < 4; k++) {
                fmaf2(accf[r][k], h2f2_pre(acch[r][k]), c112);
                acch[r][k] = 0u;
            }
    }

#pragma unroll
    for (int r = 0; r < RPW; r++) {
        int row = rbase + r;
        if (row < NB_ROWS) {
            float4 o0, o1;
            o0.x = lo32(accf[r][0]); o0.y = hi32(accf[r][0]);
            o0.z = lo32(accf[r][1]); o0.w = hi32(accf[r][1]);
            o1.x = lo32(accf[r][2]); o1.y = hi32(accf[r][2]);
            o1.z = lo32(accf[r][3]); o1.w = hi32(accf[r][3]);
            float4* dst = reinterpret_cast<float4*>(out) + row * (N_OUT / 4) + o8 * 2;
            dst[0] = o0;
            dst[1] = o1;
        }
    }
}

// ================= launch =================
extern "C" void kernel_launch(void* const* d_in, const int* in_sizes, int n_in,
                              void* d_out, int out_size) {
    const float* x  = (const float*)d_in[0];   // [16384, 256]
    const float* bw = (const float*)d_in[1];   // [256, 256]
    const float* sw = (const float*)d_in[2];   // [256, 256, 31]
    const float* sc = (const float*)d_in[3];   // [256, 256]
    float* out = (float*)d_out;

    cudaFuncSetAttribute(k_main, cudaFuncAttributeMaxDynamicSharedMemorySize, SMEM_TOTAL);

    k_init  <<<1, 256>>>();
    k_minmax<<<128, 256>>>(x);
    k_denom <<<1, 256>>>();
    k_rxj   <<<NB_ROWS / 8, 256>>>(x);
    k_pad   <<<BROWS - NB_ROWS, 256>>>();
    k_bw16  <<<dim3(8, 8), dim3(32, 8)>>>(bw);
    k_w2    <<<256, 256>>>(sw, sc);
    k_main  <<<NCTA, THREADS, SMEM_TOTAL>>>(out);
}

// round 17
// speedup vs baseline: 1.0268x; 1.0268x over previous
#include <cuda_runtime.h>
#include <cuda_fp16.h>
#include <cstdint>

// ================= problem constants =================
#define NB_ROWS  16384
#define N_IN     256
#define N_OUT    256
#define N_BASES  31
#define MTILE    112                 // rows per CTA
#define RPW      7                   // rows per warp (16 warps)
#define NCTA     147                 // ceil(16384/112)
#define BROWS    (NCTA * MTILE)      // 16464 padded rows
#define THREADS  512

// per-stage smem block: W2 (4 slices) | bw (2KB) | rj (1792B)
#define SLICE    16896               // 33 j-rows x 256 fp16
#define STAGE    (4 * SLICE)         // 67584
#define OFF_BW   STAGE               // +2048
#define OFF_RJ   (STAGE + 2048)      // +1792
#define SBUF     (STAGE + 2048 + 1792)   // 71424 per buffer
#define TOTBYTES SBUF
#define SM_MBAR  (2 * SBUF)
#define SMEM_TOTAL (2 * SBUF + 64)

// ================= device scratch =================
__device__ __align__(16) __half   g_W2T[N_IN * 33 * N_OUT];  // [i][j<=32][o] fp16
__device__ __align__(16) __half   g_BW16[N_IN * N_OUT];      // [i][o] fp16 (2KB per 4-i stage)
__device__ __align__(16) uint32_t g_RJ3[64 * BROWS * 4];     // [ib][row][u]: (j<<16)|rx_fp16
__device__ unsigned int g_minU[N_IN];
__device__ unsigned int g_maxU[N_IN];
__device__ float        g_minv[N_IN];
__device__ float        g_rcp[N_IN];

// ================= helpers =================
__device__ __forceinline__ unsigned int enc_f(float f) {
    unsigned int u = __float_as_uint(f);
    return (u & 0x80000000u) ? ~u : (u | 0x80000000u);
}
__device__ __forceinline__ float dec_f(unsigned int e) {
    unsigned int u = (e & 0x80000000u) ? (e ^ 0x80000000u) : ~e;
    return __uint_as_float(u);
}
__device__ __forceinline__ uint32_t smem_u32(const void* p) {
    uint32_t a;
    asm("{ .reg .u64 t; cvta.to.shared.u64 t, %1; cvt.u32.u64 %0, t; }" : "=r"(a) : "l"(p));
    return a;
}
__device__ __forceinline__ unsigned long long pk2(float a, float b) {
    unsigned long long r;
    asm("mov.b64 %0, {%1, %2};" : "=l"(r) : "f"(a), "f"(b));
    return r;
}
__device__ __forceinline__ unsigned long long pku(uint32_t a, uint32_t b) {
    unsigned long long r;
    asm("mov.b64 %0, {%1, %2};" : "=l"(r) : "r"(a), "r"(b));
    return r;
}
__device__ __forceinline__ void fmaf2(unsigned long long& d, unsigned long long a, unsigned long long b) {
    asm("fma.rn.f32x2 %0, %1, %2, %0;" : "+l"(d) : "l"(a), "l"(b));
}
__device__ __forceinline__ float lo32(unsigned long long v) {
    return __uint_as_float((unsigned int)(v & 0xFFFFFFFFull));
}
__device__ __forceinline__ float hi32(unsigned long long v) {
    return __uint_as_float((unsigned int)(v >> 32));
}
__device__ __forceinline__ void hadd2a(uint32_t& acc, uint32_t v) {
    asm("add.rn.f16x2 %0, %1, %0;" : "+r"(acc) : "r"(v));
}
__device__ __forceinline__ void hfma2a(uint32_t& acc, uint32_t a, uint32_t b) {
    asm("fma.rn.f16x2 %0, %1, %2, %0;" : "+r"(acc) : "r"(a), "r"(b));
}
// packed fp16x2 -> f32x2 equal to (v_lo, v_hi) * 2^-112, EXACT, ALU-only.
__device__ __forceinline__ unsigned long long h2f2_pre(uint32_t h) {
    uint32_t s = h << 16;
    uint32_t m = h & 0xFFFF0000u;
    uint32_t lo = ((s >> 3) & 0x0FFFE000u) | (s & 0x80000000u);
    uint32_t hi = ((m >> 3) & 0x0FFFE000u) | (m & 0x80000000u);
    return pku(lo, hi);
}

#define MBAR_INIT(a, c)  asm volatile("mbarrier.init.shared.b64 [%0], %1;" :: "r"(a), "r"(c) : "memory")
#define MBAR_EXPECT(a, b) asm volatile("mbarrier.arrive.expect_tx.shared.b64 _, [%0], %1;" :: "r"(a), "r"(b) : "memory")
#define MBAR_WAIT(a, ph) do {                                                        \
    uint32_t _m = (a), _p = (ph), _d;                                                \
    asm volatile("{\n\t.reg .pred p;\n\t"                                            \
        "mbarrier.try_wait.parity.acquire.cta.shared::cta.b64 p, [%1], %2;\n\t"      \
        "selp.b32 %0,1,0,p;\n\t}" : "=r"(_d) : "r"(_m), "r"(_p) : "memory");         \
    if (!_d) {                                                                       \
        asm volatile("{\n\t.reg .pred P1;\n\tWL_%=:\n\t"                             \
            "mbarrier.try_wait.parity.acquire.cta.shared::cta.b64 P1, [%0], %1, 0x989680;\n\t" \
            "@P1 bra.uni WD_%=;\n\tbra.uni WL_%=;\n\tWD_%=:\n\t}"                    \
            :: "r"(_m), "r"(_p) : "memory");                                         \
    }                                                                                \
} while (0)
#define BULK_CP(dst, src, bytes, mbar) \
    asm volatile("cp.async.bulk.shared::cluster.global.mbarrier::complete_tx::bytes [%0], [%1], %2, [%3];" \
        :: "r"(dst), "l"(src), "r"(bytes), "r"(mbar) : "memory")

// ================= prep kernels =================
__global__ void k_init() {
    int t = threadIdx.x;
    g_minU[t] = 0xFFFFFFFFu;
    g_maxU[t] = 0x00000000u;
}

__global__ void k_minmax(const float* __restrict__ x) {
    int c  = threadIdx.x;
    int r0 = blockIdx.x * 128;
    float mn = __int_as_float(0x7f800000);
    float mx = __int_as_float(0xff800000);
    for (int r = r0; r < r0 + 128; r++) {
        float v = x[r * N_IN + c];
        mn = fminf(mn, v);
        mx = fmaxf(mx, v);
    }
    atomicMin(&g_minU[c], enc_f(mn));
    atomicMax(&g_maxU[c], enc_f(mx));
}

__global__ void k_denom() {   // XLA rewrites div(A,bcast(B)) -> mul(A,bcast(1/B))
    int i = threadIdx.x;
    float mn = dec_f(g_minU[i]);
    float mx = dec_f(g_maxU[i]);
    float d  = __fadd_rn(__fsub_rn(mx, mn), 1e-8f);
    g_minv[i] = mn;
    g_rcp[i]  = __frcp_rn(d);
}

// bucketize + relu fp16 -> g_RJ3[i>>2][row][i&3] (stage-major for bulk prefetch)
__global__ void k_rxj(const float* __restrict__ x) {
    int i  = threadIdx.x;
    int r0 = blockIdx.x * 8;
    float mn = g_minv[i];
    float rc = g_rcp[i];
    uint32_t* dst = g_RJ3 + ((size_t)(i >> 2) * BROWS) * 4 + (i & 3);
#pragma unroll
    for (int k = 0; k < 8; k++) {
        int r = r0 + k;
        float v  = x[r * N_IN + i];
        float xn = __fmul_rn(__fsub_rn(v, mn), rc);   // bit-matches reference
        int j = (int)(xn * 32.0f);
        j = min(max(j, 0), 32);
        unsigned short h = __half_as_ushort(__float2half_rn(fmaxf(v, 0.0f)));
        dst[(size_t)r * 4] = ((uint32_t)j << 16) | (uint32_t)h;
    }
}

// pad rows [16384, 16464): j=32 (zero W2 row), rx=0
__global__ void k_pad() {
    int i   = threadIdx.x;
    int row = NB_ROWS + blockIdx.x;
    g_RJ3[((size_t)(i >> 2) * BROWS + row) * 4 + (i & 3)] = (32u << 16);
}

// transpose base_weight [o][i] -> g_BW16 [i][o] fp16
__global__ void k_bw16(const float* __restrict__ bw) {
    __shared__ float s[32][33];
    int tx = threadIdx.x, ty = threadIdx.y;
    int a0 = blockIdx.y * 32;   // o
    int b0 = blockIdx.x * 32;   // i
#pragma unroll
    for (int k = 0; k < 4; k++)
        s[ty + 8 * k][tx] = bw[(a0 + ty + 8 * k) * N_IN + b0 + tx];
    __syncthreads();
#pragma unroll
    for (int k = 0; k < 4; k++)
        g_BW16[(b0 + ty + 8 * k) * N_OUT + a0 + tx] = __float2half_rn(s[tx][ty + 8 * k]);
}

// W2T[i][j<=32][o] fp16 (j=32 row is zeros)
__global__ void k_w2(const float* __restrict__ sw, const float* __restrict__ sc) {
    int i = blockIdx.x;
    int o = threadIdx.x;
    float s = sc[o * N_IN + i];
    float w[N_BASES];
#pragma unroll
    for (int k = 0; k < N_BASES; k++)
        w[k] = sw[o * (N_IN * N_BASES) + i * N_BASES + k] * s;
    __half* dst = g_W2T + (size_t)i * 33 * N_OUT + o;
#pragma unroll
    for (int j = 0; j < 32; j++) {
        float a = 0.0f;
#pragma unroll
        for (int l = 0; l < 5; l++) {
            int shift = j >> (5 - l);
            int half  = (j >> (4 - l)) & 1;
            int k     = (1 << l) - 1 + shift;
            a += half ? -w[k] : w[k];
        }
        dst[j * N_OUT] = __float2half_rn(a);
    }
    dst[32 * N_OUT] = __ushort_as_half(0);   // zero row for j == 32
}

// ================= main kernel =================
// 147 CTAs x 512 threads. Per 4-i stage, THREE cp.async.bulk prefetch W2+bw+rj
// into the alternating smem buffer; the hot loop issues ZERO global loads.
__global__ __launch_bounds__(THREADS, 1) void k_main(float* __restrict__ out) {
    extern __shared__ char smem[];
    const uint32_t sb = smem_u32(smem);
    const int tid   = threadIdx.x;
    const int o8    = tid & 31;
    const int w     = tid >> 5;
    const int rbase = blockIdx.x * MTILE + w * RPW;
    const unsigned long long c112 = pk2(__uint_as_float(0x77800000u),   // 2^112
                                        __uint_as_float(0x77800000u));

    if (tid == 0) {
        MBAR_INIT(sb + SM_MBAR,     1);
        MBAR_INIT(sb + SM_MBAR + 8, 1);
    }
    __syncthreads();

    unsigned long long accf[RPW][4];
    uint32_t acch[RPW][4];
#pragma unroll
    for (int r = 0; r < RPW; r++)
#pragma unroll
        for (int k = 0; k < 4; k++) { accf[r][k] = 0ull; acch[r][k] = 0u; }

    const char* w2 = reinterpret_cast<const char*>(g_W2T);
    const char* bw = reinterpret_cast<const char*>(g_BW16);
    const char* rj = reinterpret_cast<const char*>(g_RJ3) + (size_t)blockIdx.x * MTILE * 16;

    if (tid == 0) {
        MBAR_EXPECT(sb + SM_MBAR, TOTBYTES);
        BULK_CP(sb,          w2, STAGE, sb + SM_MBAR);
        BULK_CP(sb + OFF_BW, bw, 2048,  sb + SM_MBAR);
        BULK_CP(sb + OFF_RJ, rj, 1792,  sb + SM_MBAR);
    }

    for (int ib = 0; ib < 64; ib++) {
        __syncthreads();                       // readers of the other stage done
        if (tid == 0 && ib + 1 < 64) {
            uint32_t mb = sb + SM_MBAR + 8 * ((ib + 1) & 1);
            uint32_t db = sb + ((ib + 1) & 1) * SBUF;
            MBAR_EXPECT(mb, TOTBYTES);
            BULK_CP(db,          w2 + (size_t)(ib + 1) * STAGE, STAGE, mb);
            BULK_CP(db + OFF_BW, bw + (size_t)(ib + 1) * 2048,  2048,  mb);
            BULK_CP(db + OFF_RJ, rj + (size_t)(ib + 1) * (BROWS * 16), 1792, mb);
        }
        MBAR_WAIT(sb + SM_MBAR + 8 * (ib & 1), (ib >> 1) & 1);
        const uint32_t stg = sb + (ib & 1) * SBUF;

        // base weights for the 4 i of this stage (from smem)
        uint4 bwv[4];
#pragma unroll
        for (int u = 0; u < 4; u++)
            asm("ld.shared.v4.u32 {%0,%1,%2,%3}, [%4];"
                : "=r"(bwv[u].x), "=r"(bwv[u].y), "=r"(bwv[u].z), "=r"(bwv[u].w)
                : "r"(stg + OFF_BW + u * 512 + o8 * 16));

#pragma unroll
        for (int r = 0; r < RPW; r++) {
            // rj for the 4 i of this stage, local row w*7+r (uniform broadcast LDS)
            uint4 q;
            asm("ld.shared.v4.u32 {%0,%1,%2,%3}, [%4];"
                : "=r"(q.x), "=r"(q.y), "=r"(q.z), "=r"(q.w)
                : "r"(stg + OFF_RJ + (w * RPW + r) * 16));
            uint32_t qa[4] = { q.x, q.y, q.z, q.w };
#pragma unroll
            for (int u = 0; u < 4; u++) {
                uint32_t rjv = qa[u];
                uint32_t a   = stg + u * SLICE + (rjv >> 16) * 512 + o8 * 16;  // j==32 -> zero row
                uint4 gv;
                asm("ld.shared.v4.u32 {%0,%1,%2,%3}, [%4];"
                    : "=r"(gv.x), "=r"(gv.y), "=r"(gv.z), "=r"(gv.w) : "r"(a));
                uint32_t rxd;
                asm("prmt.b32 %0, %1, %1, 0x1010;" : "=r"(rxd) : "r"(rjv));   // splat rx half
                hadd2a(acch[r][0], gv.x);  hfma2a(acch[r][0], bwv[u].x, rxd);
                hadd2a(acch[r][1], gv.y);  hfma2a(acch[r][1], bwv[u].y, rxd);
                hadd2a(acch[r][2], gv.z);  hfma2a(acch[r][2], bwv[u].z, rxd);
                hadd2a(acch[r][3], gv.w);  hfma2a(acch[r][3], bwv[u].w, rxd);
            }
        }
        // flush fp16 group (4 i) into f32 accumulators — exact ALU unpack + fma x 2^112
#pragma unroll
        for (int r = 0; r < RPW; r++)
#pragma unroll
            for (int k = 0; k < 4; k++) {
                fmaf2(accf[r][k], h2f2_pre(acch[r][k]), c112);
                acch[r][k] = 0u;
            }
    }

#pragma unroll
    for (int r = 0; r < RPW; r++) {
        int row = rbase + r;
        if (row < NB_ROWS) {
            float4 o0, o1;
            o0.x = lo32(accf[r][0]); o0.y = hi32(accf[r][0]);
            o0.z = lo32(accf[r][1]); o0.w = hi32(accf[r][1]);
            o1.x = lo32(accf[r][2]); o1.y = hi32(accf[r][2]);
            o1.z = lo32(accf[r][3]); o1.w = hi32(accf[r][3]);
            float4* dst = reinterpret_cast<float4*>(out) + row * (N_OUT / 4) + o8 * 2;
            dst[0] = o0;
            dst[1] = o1;
        }
    }
}

// ================= launch =================
extern "C" void kernel_launch(void* const* d_in, const int* in_sizes, int n_in,
                              void* d_out, int out_size) {
    const float* x  = (const float*)d_in[0];   // [16384, 256]
    const float* bw = (const float*)d_in[1];   // [256, 256]
    const float* sw = (const float*)d_in[2];   // [256, 256, 31]
    const float* sc = (const float*)d_in[3];   // [256, 256]
    float* out = (float*)d_out;

    cudaFuncSetAttribute(k_main, cudaFuncAttributeMaxDynamicSharedMemorySize, SMEM_TOTAL);

    k_init  <<<1, 256>>>();
    k_minmax<<<128, 256>>>(x);
    k_denom <<<1, 256>>>();
    k_rxj   <<<NB_ROWS / 8, 256>>>(x);
    k_pad   <<<BROWS - NB_ROWS, 256>>>();
    k_bw16  <<<dim3(8, 8), dim3(32, 8)>>>(bw);
    k_w2    <<<256, 256>>>(sw, sc);
    k_main  <<<NCTA, THREADS, SMEM_TOTAL>>>(out);
}